// round 1
// baseline (speedup 1.0000x reference)
#include <cuda_runtime.h>
#include <cstdint>
#include <cstddef>

#define BQ 2
#define QL 1024
#define ML 1024
#define KL 2048
#define DM 1024
#define NH 16
#define DH 64

// ---------------- scratch (device globals: allocation-free) ----------------
__device__ float g_w[(size_t)4096 * 3072];        // cat @ W_qkv  [B*K, 3D]
__device__ float g_rp[(size_t)4096 * 1024];       // r @ W_r      [B*K, D]
__device__ float g_score[(size_t)32 * 1024 * 2048]; // [B*H, Q, K] scores -> probs
__device__ float g_attn[(size_t)2048 * 1024];     // [B*Q, D] pre-W_o

// ====================== SGEMM: C[MR,N] = A @ W[1024,N] + bias ==============
// MODE 0: A = concat(mem, inputs) rows (B*K x D).  MODE 1: A = A0 directly.
template<int MODE>
__global__ __launch_bounds__(256, 2)
void sgemm_kernel(const float* __restrict__ A0, const float* __restrict__ A1,
                  const float* __restrict__ W, const float* __restrict__ bias,
                  float* __restrict__ C, int N)
{
    __shared__ float As[8][128];
    __shared__ float Bs[8][128];
    const int t  = threadIdx.x;
    const int m0 = blockIdx.y * 128;
    const int n0 = blockIdx.x * 128;

    const int arow = t >> 1;
    const int akq  = (t & 1) * 4;
    const int grow = m0 + arow;
    const float* aptr;
    if (MODE == 0) {
        int b = grow >> 11;
        int k = grow & 2047;
        aptr = (k < ML) ? (A0 + (size_t)(b * ML + k) * DM)
                        : (A1 + (size_t)(b * QL + (k - ML)) * DM);
    } else {
        aptr = A0 + (size_t)grow * DM;
    }
    const int brow = t >> 5;
    const int bcol = (t & 31) * 4;
    const float* wptr = W + (size_t)brow * N + n0 + bcol;

    const int tm = (t >> 4) * 8;
    const int tn = (t & 15) * 8;

    float acc[8][8];
#pragma unroll
    for (int i = 0; i < 8; ++i)
#pragma unroll
        for (int j = 0; j < 8; ++j) acc[i][j] = 0.f;

    float4 av = *(const float4*)(aptr + akq);
    float4 bv = *(const float4*)(wptr);

    for (int k0 = 0; k0 < DM; k0 += 8) {
        As[akq + 0][arow] = av.x;
        As[akq + 1][arow] = av.y;
        As[akq + 2][arow] = av.z;
        As[akq + 3][arow] = av.w;
        *(float4*)&Bs[brow][bcol] = bv;
        __syncthreads();
        if (k0 + 8 < DM) {
            av = *(const float4*)(aptr + k0 + 8 + akq);
            bv = *(const float4*)(wptr + (size_t)(k0 + 8) * N);
        }
#pragma unroll
        for (int kk = 0; kk < 8; ++kk) {
            float a[8], b[8];
            *(float4*)(a)     = *(const float4*)&As[kk][tm];
            *(float4*)(a + 4) = *(const float4*)&As[kk][tm + 4];
            *(float4*)(b)     = *(const float4*)&Bs[kk][tn];
            *(float4*)(b + 4) = *(const float4*)&Bs[kk][tn + 4];
#pragma unroll
            for (int i = 0; i < 8; ++i)
#pragma unroll
                for (int j = 0; j < 8; ++j)
                    acc[i][j] = fmaf(a[i], b[j], acc[i][j]);
        }
        __syncthreads();
    }

    float bvals[8];
#pragma unroll
    for (int j = 0; j < 8; ++j) bvals[j] = bias[n0 + tn + j];
#pragma unroll
    for (int i = 0; i < 8; ++i) {
        size_t off = (size_t)(m0 + tm + i) * N + n0 + tn;
        float4 o0, o1;
        o0.x = acc[i][0] + bvals[0]; o0.y = acc[i][1] + bvals[1];
        o0.z = acc[i][2] + bvals[2]; o0.w = acc[i][3] + bvals[3];
        o1.x = acc[i][4] + bvals[4]; o1.y = acc[i][5] + bvals[5];
        o1.z = acc[i][6] + bvals[6]; o1.w = acc[i][7] + bvals[7];
        *(float4*)(C + off)     = o0;
        *(float4*)(C + off + 4) = o1;
    }
}

// ================== AC / BD score kernels ==================================
// AC (!IS_BD): score[bh,i,j]  = sum_d (hq[i,d]+u[d]) * hk[j,d]
// BD ( IS_BD): score[bh,i,j] += sum_d (hq[i,d]+v[d]) * hr[p,d],  j = p+i-(Q-1)
template<bool IS_BD>
__global__ __launch_bounds__(256, 2)
void score_kernel(const float* __restrict__ u, const float* __restrict__ v)
{
    const int bh = blockIdx.z;
    const int b  = bh >> 4;
    const int h  = bh & 15;
    const int i0 = blockIdx.y * 128;
    const int p0 = blockIdx.x * 128;
    if (!IS_BD) {
        if (p0 > ML + i0 + 127) return;                 // fully masked tile
    } else {
        if (p0 + 127 < (QL - 1) - (i0 + 127)) return;   // all targets j < 0
    }

    __shared__ float As[32][128];
    __shared__ float Bs[32][128];
    const int t    = threadIdx.x;
    const int lrow = t >> 1;
    const int ldq  = (t & 1) * 4;
    const float* uv = (IS_BD ? v : u) + h * DH;
    const int tm = (t >> 4) * 8;
    const int tn = (t & 15) * 8;

    float acc[8][8];
#pragma unroll
    for (int i = 0; i < 8; ++i)
#pragma unroll
        for (int j = 0; j < 8; ++j) acc[i][j] = 0.f;

    const float* abase = g_w + (size_t)(b * KL + ML + i0 + lrow) * 3072 + h * DH;
    const float* bbase;
    if (!IS_BD)
        bbase = g_w  + (size_t)(b * KL + p0 + lrow) * 3072 + 2 * DM + h * DH;
    else
        bbase = g_rp + (size_t)(b * KL + p0 + lrow) * DM + h * DH;

    for (int dc = 0; dc < DH; dc += 32) {
#pragma unroll
        for (int it = 0; it < 4; ++it) {
            int d = ldq + it * 8;                 // 0..31, 4-aligned
            float4 a4 = *(const float4*)(abase + dc + d);
            a4.x += uv[dc + d + 0];
            a4.y += uv[dc + d + 1];
            a4.z += uv[dc + d + 2];
            a4.w += uv[dc + d + 3];
            As[d + 0][lrow] = a4.x;
            As[d + 1][lrow] = a4.y;
            As[d + 2][lrow] = a4.z;
            As[d + 3][lrow] = a4.w;
            float4 b4 = *(const float4*)(bbase + dc + d);
            Bs[d + 0][lrow] = b4.x;
            Bs[d + 1][lrow] = b4.y;
            Bs[d + 2][lrow] = b4.z;
            Bs[d + 3][lrow] = b4.w;
        }
        __syncthreads();
#pragma unroll 8
        for (int kk = 0; kk < 32; ++kk) {
            float a[8], bb[8];
            *(float4*)(a)      = *(const float4*)&As[kk][tm];
            *(float4*)(a + 4)  = *(const float4*)&As[kk][tm + 4];
            *(float4*)(bb)     = *(const float4*)&Bs[kk][tn];
            *(float4*)(bb + 4) = *(const float4*)&Bs[kk][tn + 4];
#pragma unroll
            for (int i = 0; i < 8; ++i)
#pragma unroll
                for (int j = 0; j < 8; ++j)
                    acc[i][j] = fmaf(a[i], bb[j], acc[i][j]);
        }
        __syncthreads();
    }

    if (!IS_BD) {
#pragma unroll
        for (int i = 0; i < 8; ++i) {
            size_t off = ((size_t)bh * QL + (i0 + tm + i)) * KL + p0 + tn;
            float4 o0, o1;
            o0.x = acc[i][0]; o0.y = acc[i][1]; o0.z = acc[i][2]; o0.w = acc[i][3];
            o1.x = acc[i][4]; o1.y = acc[i][5]; o1.z = acc[i][6]; o1.w = acc[i][7];
            *(float4*)(g_score + off)     = o0;
            *(float4*)(g_score + off + 4) = o1;
        }
    } else {
#pragma unroll
        for (int i = 0; i < 8; ++i) {
            int gi = i0 + tm + i;
            float* srow = g_score + ((size_t)bh * QL + gi) * KL;
            int jbase = p0 + tn + gi - (QL - 1);   // j = p + i - (Q-1); always < K
#pragma unroll
            for (int c = 0; c < 8; ++c) {
                int j = jbase + c;
                if (j >= 0) srow[j] += acc[i][c];
            }
        }
    }
}

// ========================= softmax (masked, scaled) =========================
__global__ __launch_bounds__(256)
void softmax_kernel()
{
    const size_t row = blockIdx.x;              // 0 .. B*H*Q-1
    const int i = (int)(row & (QL - 1));
    float* s = g_score + row * KL;
    const int valid = ML + i + 1;               // j in [0, valid)
    const int t = threadIdx.x;
    __shared__ float red[256];

    float mx = -3.0e38f;
    for (int j = t; j < valid; j += 256) mx = fmaxf(mx, s[j]);
    red[t] = mx; __syncthreads();
#pragma unroll
    for (int o = 128; o > 0; o >>= 1) {
        if (t < o) red[t] = fmaxf(red[t], red[t + o]);
        __syncthreads();
    }
    mx = red[0];
    __syncthreads();

    float ev[8];
    float sum = 0.f;
    int cnt = 0;
    for (int j = t; j < valid; j += 256) {
        float e = __expf(0.125f * (s[j] - mx));
        ev[cnt++] = e;
        sum += e;
    }
    red[t] = sum; __syncthreads();
#pragma unroll
    for (int o = 128; o > 0; o >>= 1) {
        if (t < o) red[t] += red[t + o];
        __syncthreads();
    }
    const float inv = 1.f / red[0];

    cnt = 0;
    for (int j = t; j < valid; j += 256) s[j] = ev[cnt++] * inv;
    for (int j = t; j < KL; j += 256)
        if (j >= valid) s[j] = 0.f;
}

// ========================= P @ V ===========================================
// out[b, i, h*64+d] = sum_j P[bh,i,j] * hv[j,d]
__global__ __launch_bounds__(256, 2)
void pv_kernel()
{
    const int bh = blockIdx.y;
    const int b  = bh >> 4;
    const int h  = bh & 15;
    const int i0 = blockIdx.x * 64;

    __shared__ float Ps[64][64];   // [j][i] transposed
    __shared__ float Vs[64][64];   // [j][d]

    const int t    = threadIdx.x;
    const int lrow = t >> 2;       // 0..63
    const int lq   = (t & 3) * 4;
    const int tm   = (t >> 4) * 4; // i micro base
    const int tn   = (t & 15) * 4; // d micro base

    float acc[4][4];
#pragma unroll
    for (int i = 0; i < 4; ++i)
#pragma unroll
        for (int j = 0; j < 4; ++j) acc[i][j] = 0.f;

    const int jend = ML + i0 + 64;   // multiple of 64, <= KL; P is 0 beyond mask
    const float* prow  = g_score + ((size_t)bh * QL + i0 + lrow) * KL;
    const float* vbase = g_w + (size_t)(b * KL) * 3072 + DM + h * DH;

    for (int j0 = 0; j0 < jend; j0 += 64) {
#pragma unroll
        for (int it = 0; it < 4; ++it) {
            int jj = lq + it * 16;
            float4 p4 = *(const float4*)(prow + j0 + jj);
            Ps[jj + 0][lrow] = p4.x;
            Ps[jj + 1][lrow] = p4.y;
            Ps[jj + 2][lrow] = p4.z;
            Ps[jj + 3][lrow] = p4.w;
            int d = lq + it * 16;
            float4 v4 = *(const float4*)(vbase + (size_t)(j0 + lrow) * 3072 + d);
            *(float4*)&Vs[lrow][d] = v4;
        }
        __syncthreads();
#pragma unroll 16
        for (int jj = 0; jj < 64; ++jj) {
            float a[4], bb[4];
            *(float4*)a  = *(const float4*)&Ps[jj][tm];
            *(float4*)bb = *(const float4*)&Vs[jj][tn];
#pragma unroll
            for (int i = 0; i < 4; ++i)
#pragma unroll
                for (int j = 0; j < 4; ++j)
                    acc[i][j] = fmaf(a[i], bb[j], acc[i][j]);
        }
        __syncthreads();
    }

#pragma unroll
    for (int i = 0; i < 4; ++i) {
        size_t off = ((size_t)(b * QL) + i0 + tm + i) * DM + h * DH + tn;
        float4 o;
        o.x = acc[i][0]; o.y = acc[i][1]; o.z = acc[i][2]; o.w = acc[i][3];
        *(float4*)(g_attn + off) = o;
    }
}

// =========================== launch =======================================
extern "C" void kernel_launch(void* const* d_in, const int* in_sizes, int n_in,
                              void* d_out, int out_size)
{
    const float* inputs = (const float*)d_in[0];
    const float* mem    = (const float*)d_in[1];
    const float* r      = (const float*)d_in[2];
    const float* W_qkv  = (const float*)d_in[3];
    const float* b_qkv  = (const float*)d_in[4];
    const float* W_r    = (const float*)d_in[5];
    const float* b_r    = (const float*)d_in[6];
    const float* W_o    = (const float*)d_in[7];
    const float* b_o    = (const float*)d_in[8];
    const float* u      = (const float*)d_in[9];
    const float* v      = (const float*)d_in[10];
    float* out = (float*)d_out;

    float *pw = nullptr, *prp = nullptr, *pattn = nullptr;
    cudaGetSymbolAddress((void**)&pw,    g_w);
    cudaGetSymbolAddress((void**)&prp,   g_rp);
    cudaGetSymbolAddress((void**)&pattn, g_attn);

    dim3 blk(256);

    // 1) w = cat(mem, inputs) @ W_qkv + b_qkv   -> g_w [4096, 3072]
    sgemm_kernel<0><<<dim3(3072 / 128, 4096 / 128), blk>>>(mem, inputs, W_qkv, b_qkv, pw, 3072);
    // 2) rp = r @ W_r + b_r                     -> g_rp [4096, 1024]
    sgemm_kernel<1><<<dim3(1024 / 128, 4096 / 128), blk>>>(r, nullptr, W_r, b_r, prp, 1024);
    // 3) AC content scores
    score_kernel<false><<<dim3(KL / 128, QL / 128, BQ * NH), blk>>>(u, v);
    // 4) BD position scores, scatter-added at rel-shifted location
    score_kernel<true><<<dim3(KL / 128, QL / 128, BQ * NH), blk>>>(u, v);
    // 5) masked scaled softmax (in place -> probabilities)
    softmax_kernel<<<BQ * NH * QL, blk>>>();
    // 6) out_heads = P @ V                      -> g_attn [2048, 1024]
    pv_kernel<<<dim3(QL / 64, BQ * NH), blk>>>();
    // 7) final projection: g_attn @ W_o + b_o   -> d_out
    sgemm_kernel<1><<<dim3(1024 / 128, 2048 / 128), blk>>>(pattn, nullptr, W_o, b_o, out, 1024);
}

// round 3
// speedup vs baseline: 1.3698x; 1.3698x over previous
#include <cuda_runtime.h>
#include <cuda_bf16.h>
#include <cstdint>
#include <cstddef>

#define BQ 2
#define QL 1024
#define ML 1024
#define KL 2048
#define DM 1024
#define NH 16
#define DH 64

// ---------------- scratch (device globals: allocation-free) ----------------
__device__ float g_w[(size_t)4096 * 3072];          // cat @ W_qkv  [B*K, 3D]
__device__ float g_rp[(size_t)4096 * 1024];         // r @ W_r      [B*K, D]
__device__ float g_score[(size_t)32 * 1024 * 2048]; // [B*H, Q, K]
__device__ float g_attn[(size_t)2048 * 1024];       // [B*Q, D]

// bf16 hi/lo split buffers (A-side activations and K-major weights)
__device__ __nv_bfloat16 g_ah[(size_t)4096 * 1024], g_al[(size_t)4096 * 1024];
__device__ __nv_bfloat16 g_rh[(size_t)4096 * 1024], g_rl[(size_t)4096 * 1024];
__device__ __nv_bfloat16 g_oh[(size_t)2048 * 1024], g_ol[(size_t)2048 * 1024];
__device__ __nv_bfloat16 g_wqh[(size_t)3072 * 1024], g_wql[(size_t)3072 * 1024];
__device__ __nv_bfloat16 g_wrh[(size_t)1024 * 1024], g_wrl[(size_t)1024 * 1024];
__device__ __nv_bfloat16 g_woh[(size_t)1024 * 1024], g_wol[(size_t)1024 * 1024];

// ======================= helpers ===========================================
__device__ __forceinline__ uint32_t smem_u32(const void* p) {
    uint32_t a;
    asm("{ .reg .u64 t; cvta.to.shared.u64 t, %1; cvt.u32.u64 %0, t; }"
        : "=r"(a) : "l"(p));
    return a;
}

__device__ __forceinline__ void split1(float x, __nv_bfloat16& h, __nv_bfloat16& l) {
    h = __float2bfloat16_rn(x);
    l = __float2bfloat16_rn(x - __bfloat162float(h));
}

__device__ __forceinline__ void ldmx4(uint32_t a[4], uint32_t addr) {
    asm volatile("ldmatrix.sync.aligned.m8n8.x4.shared.b16 {%0,%1,%2,%3}, [%4];"
        : "=r"(a[0]), "=r"(a[1]), "=r"(a[2]), "=r"(a[3]) : "r"(addr));
}
__device__ __forceinline__ void ldmx2(uint32_t a[2], uint32_t addr) {
    asm volatile("ldmatrix.sync.aligned.m8n8.x2.shared.b16 {%0,%1}, [%2];"
        : "=r"(a[0]), "=r"(a[1]) : "r"(addr));
}
__device__ __forceinline__ void mma16816(float c[4], const uint32_t a[4], const uint32_t b[2]) {
    asm volatile("mma.sync.aligned.m16n8k16.row.col.f32.bf16.bf16.f32 "
        "{%0,%1,%2,%3}, {%4,%5,%6,%7}, {%8,%9}, {%0,%1,%2,%3};"
        : "+f"(c[0]), "+f"(c[1]), "+f"(c[2]), "+f"(c[3])
        : "r"(a[0]), "r"(a[1]), "r"(a[2]), "r"(a[3]), "r"(b[0]), "r"(b[1]));
}

// ===================== prep: split / transpose kernels ======================
__global__ __launch_bounds__(256)
void split_concat(const float* __restrict__ mem, const float* __restrict__ inp,
                  __nv_bfloat16* __restrict__ hi, __nv_bfloat16* __restrict__ lo)
{
    size_t idx = ((size_t)blockIdx.x * 256 + threadIdx.x) * 4;
    size_t row = idx >> 10;
    int col = (int)(idx & 1023);
    int b = (int)(row >> 11);
    int k = (int)(row & 2047);
    const float* src = (k < ML) ? mem + ((size_t)(b * ML + k) << 10)
                                : inp + ((size_t)(b * QL + (k - ML)) << 10);
    float4 v = *(const float4*)(src + col);
    __nv_bfloat16 h0, h1, h2, h3, l0, l1, l2, l3;
    split1(v.x, h0, l0); split1(v.y, h1, l1);
    split1(v.z, h2, l2); split1(v.w, h3, l3);
    __nv_bfloat162* H = (__nv_bfloat162*)(hi + idx);
    __nv_bfloat162* L = (__nv_bfloat162*)(lo + idx);
    H[0] = make_bfloat162(h0, h1); H[1] = make_bfloat162(h2, h3);
    L[0] = make_bfloat162(l0, l1); L[1] = make_bfloat162(l2, l3);
}

__global__ __launch_bounds__(256)
void split_plain(const float* __restrict__ src,
                 __nv_bfloat16* __restrict__ hi, __nv_bfloat16* __restrict__ lo)
{
    size_t idx = ((size_t)blockIdx.x * 256 + threadIdx.x) * 4;
    float4 v = *(const float4*)(src + idx);
    __nv_bfloat16 h0, h1, h2, h3, l0, l1, l2, l3;
    split1(v.x, h0, l0); split1(v.y, h1, l1);
    split1(v.z, h2, l2); split1(v.w, h3, l3);
    __nv_bfloat162* H = (__nv_bfloat162*)(hi + idx);
    __nv_bfloat162* L = (__nv_bfloat162*)(lo + idx);
    H[0] = make_bfloat162(h0, h1); H[1] = make_bfloat162(h2, h3);
    L[0] = make_bfloat162(l0, l1); L[1] = make_bfloat162(l2, l3);
}

// W[1024, N] -> Wt_hi/lo [N, 1024]  (K-major for the mma B operand)
__global__ __launch_bounds__(256)
void split_transpose(const float* __restrict__ in,
                     __nv_bfloat16* __restrict__ hi, __nv_bfloat16* __restrict__ lo, int N)
{
    __shared__ float s[32][33];
    const int nx = blockIdx.x * 32;
    const int ky = blockIdx.y * 32;
    const int tx = threadIdx.x & 31;
    const int ty = threadIdx.x >> 5;
#pragma unroll
    for (int r = 0; r < 32; r += 8)
        s[ty + r][tx] = in[(size_t)(ky + ty + r) * N + nx + tx];
    __syncthreads();
#pragma unroll
    for (int r = 0; r < 32; r += 8) {
        float x = s[tx][ty + r];
        __nv_bfloat16 h, l;
        split1(x, h, l);
        size_t o = (size_t)(nx + ty + r) * DM + ky + tx;
        hi[o] = h;
        lo[o] = l;
    }
}

// ============== mma.sync bf16 3-term split GEMM ============================
// C[M, N] = A[M, 1024] @ W + bias, A/B given as bf16 hi/lo, B as W^T [N,1024].
// Block 128x128, BK=32, 4-stage cp.async pipeline, 8 warps (2m x 4n).
#define RS 80                    // smem row stride bytes (32 bf16 + 8 pad)
#define ARRB (128 * RS)          // 10240 B per array per stage
#define STGB (4 * ARRB)          // Ah, Al, Bh, Bl
#define NSTG 4
#define GEMM_SMEM (NSTG * STGB)  // 163840 B

__global__ __launch_bounds__(256, 1)
void gemm_bf3(const __nv_bfloat16* __restrict__ Ah, const __nv_bfloat16* __restrict__ Al,
              const __nv_bfloat16* __restrict__ Bh, const __nv_bfloat16* __restrict__ Bl,
              const float* __restrict__ bias, float* __restrict__ C, int N)
{
    extern __shared__ char sm[];
    const uint32_t sb = smem_u32(sm);
    const int t = threadIdx.x;
    const int lane = t & 31;
    const int wid = t >> 5;
    const int m0 = blockIdx.y * 128;
    const int n0 = blockIdx.x * 128;
    const int warp_m = (wid & 1) * 64;
    const int warp_n = (wid >> 1) * 32;

    const __nv_bfloat16* srcs[4] = {
        Ah + (size_t)m0 * DM, Al + (size_t)m0 * DM,
        Bh + (size_t)n0 * DM, Bl + (size_t)n0 * DM
    };

    auto issue_stage = [&](int c) {
        uint32_t dst0 = sb + (uint32_t)(c & 3) * STGB;
#pragma unroll
        for (int arr = 0; arr < 4; ++arr) {
#pragma unroll
            for (int rep = 0; rep < 2; ++rep) {
                int ci = t + rep * 256;         // 0..511 chunk id
                int row = ci >> 2;
                int kc = ci & 3;
                uint32_t dst = dst0 + arr * ARRB + row * RS + kc * 16;
                const __nv_bfloat16* src = srcs[arr] + (size_t)row * DM + c * 32 + kc * 8;
                asm volatile("cp.async.cg.shared.global [%0], [%1], 16;"
                             :: "r"(dst), "l"(src) : "memory");
            }
        }
    };

    float acc[4][4][4];
#pragma unroll
    for (int im = 0; im < 4; ++im)
#pragma unroll
        for (int jn = 0; jn < 4; ++jn)
#pragma unroll
            for (int q = 0; q < 4; ++q) acc[im][jn][q] = 0.f;

    // prologue: stages 0..2
#pragma unroll
    for (int s = 0; s < NSTG - 1; ++s) {
        issue_stage(s);
        asm volatile("cp.async.commit_group;" ::: "memory");
    }

    const int NCH = DM / 32;
    for (int c = 0; c < NCH; ++c) {
        asm volatile("cp.async.wait_group 2;" ::: "memory");
        __syncthreads();
        if (c + 3 < NCH) issue_stage(c + 3);
        asm volatile("cp.async.commit_group;" ::: "memory");

        const uint32_t st = sb + (uint32_t)(c & 3) * STGB;
        const int mrow = lane & 15;
        const int khalf = lane >> 4;
        const int nrow = lane & 7;
        const int khalfb = (lane >> 3) & 1;
#pragma unroll
        for (int kk = 0; kk < 32; kk += 16) {
            uint32_t ah[4][4], al[4][4], bh[4][2], bl[4][2];
#pragma unroll
            for (int im = 0; im < 4; ++im) {
                uint32_t aaddr = st + (warp_m + im * 16 + mrow) * RS + (kk + khalf * 8) * 2;
                ldmx4(ah[im], aaddr);
                ldmx4(al[im], aaddr + ARRB);
            }
#pragma unroll
            for (int jn = 0; jn < 4; ++jn) {
                uint32_t baddr = st + 2 * ARRB + (warp_n + jn * 8 + nrow) * RS + (kk + khalfb * 8) * 2;
                ldmx2(bh[jn], baddr);
                ldmx2(bl[jn], baddr + ARRB);
            }
#pragma unroll
            for (int im = 0; im < 4; ++im)
#pragma unroll
                for (int jn = 0; jn < 4; ++jn) {
                    mma16816(acc[im][jn], ah[im], bh[jn]);
                    mma16816(acc[im][jn], ah[im], bl[jn]);
                    mma16816(acc[im][jn], al[im], bh[jn]);
                }
        }
    }

    // epilogue
#pragma unroll
    for (int im = 0; im < 4; ++im) {
        int m = m0 + warp_m + im * 16 + (lane >> 2);
#pragma unroll
        for (int jn = 0; jn < 4; ++jn) {
            int n = n0 + warp_n + jn * 8 + (lane & 3) * 2;
            float b0 = bias[n], b1 = bias[n + 1];
            float2 v0, v1;
            v0.x = acc[im][jn][0] + b0; v0.y = acc[im][jn][1] + b1;
            v1.x = acc[im][jn][2] + b0; v1.y = acc[im][jn][3] + b1;
            *(float2*)(C + (size_t)m * N + n) = v0;
            *(float2*)(C + (size_t)(m + 8) * N + n) = v1;
        }
    }
}

// ================== AC / BD score kernels (fp32, unchanged) =================
template<bool IS_BD>
__global__ __launch_bounds__(256, 2)
void score_kernel(const float* __restrict__ u, const float* __restrict__ v)
{
    const int bh = blockIdx.z;
    const int b  = bh >> 4;
    const int h  = bh & 15;
    const int i0 = blockIdx.y * 128;
    const int p0 = blockIdx.x * 128;
    if (!IS_BD) {
        if (p0 > ML + i0 + 127) return;
    } else {
        if (p0 + 127 < (QL - 1) - (i0 + 127)) return;
    }

    __shared__ float As[32][128];
    __shared__ float Bs[32][128];
    const int t    = threadIdx.x;
    const int lrow = t >> 1;
    const int ldq  = (t & 1) * 4;
    const float* uv = (IS_BD ? v : u) + h * DH;
    const int tm = (t >> 4) * 8;
    const int tn = (t & 15) * 8;

    float acc[8][8];
#pragma unroll
    for (int i = 0; i < 8; ++i)
#pragma unroll
        for (int j = 0; j < 8; ++j) acc[i][j] = 0.f;

    const float* abase = g_w + (size_t)(b * KL + ML + i0 + lrow) * 3072 + h * DH;
    const float* bbase;
    if (!IS_BD)
        bbase = g_w  + (size_t)(b * KL + p0 + lrow) * 3072 + 2 * DM + h * DH;
    else
        bbase = g_rp + (size_t)(b * KL + p0 + lrow) * DM + h * DH;

    for (int dc = 0; dc < DH; dc += 32) {
#pragma unroll
        for (int it = 0; it < 4; ++it) {
            int d = ldq + it * 8;
            float4 a4 = *(const float4*)(abase + dc + d);
            a4.x += uv[dc + d + 0];
            a4.y += uv[dc + d + 1];
            a4.z += uv[dc + d + 2];
            a4.w += uv[dc + d + 3];
            As[d + 0][lrow] = a4.x;
            As[d + 1][lrow] = a4.y;
            As[d + 2][lrow] = a4.z;
            As[d + 3][lrow] = a4.w;
            float4 b4 = *(const float4*)(bbase + dc + d);
            Bs[d + 0][lrow] = b4.x;
            Bs[d + 1][lrow] = b4.y;
            Bs[d + 2][lrow] = b4.z;
            Bs[d + 3][lrow] = b4.w;
        }
        __syncthreads();
#pragma unroll 8
        for (int kk = 0; kk < 32; ++kk) {
            float a[8], bb[8];
            *(float4*)(a)      = *(const float4*)&As[kk][tm];
            *(float4*)(a + 4)  = *(const float4*)&As[kk][tm + 4];
            *(float4*)(bb)     = *(const float4*)&Bs[kk][tn];
            *(float4*)(bb + 4) = *(const float4*)&Bs[kk][tn + 4];
#pragma unroll
            for (int i = 0; i < 8; ++i)
#pragma unroll
                for (int j = 0; j < 8; ++j)
                    acc[i][j] = fmaf(a[i], bb[j], acc[i][j]);
        }
        __syncthreads();
    }

    if (!IS_BD) {
#pragma unroll
        for (int i = 0; i < 8; ++i) {
            size_t off = ((size_t)bh * QL + (i0 + tm + i)) * KL + p0 + tn;
            float4 o0, o1;
            o0.x = acc[i][0]; o0.y = acc[i][1]; o0.z = acc[i][2]; o0.w = acc[i][3];
            o1.x = acc[i][4]; o1.y = acc[i][5]; o1.z = acc[i][6]; o1.w = acc[i][7];
            *(float4*)(g_score + off)     = o0;
            *(float4*)(g_score + off + 4) = o1;
        }
    } else {
#pragma unroll
        for (int i = 0; i < 8; ++i) {
            int gi = i0 + tm + i;
            float* srow = g_score + ((size_t)bh * QL + gi) * KL;
            int jbase = p0 + tn + gi - (QL - 1);
#pragma unroll
            for (int c = 0; c < 8; ++c) {
                int j = jbase + c;
                if (j >= 0) srow[j] += acc[i][c];
            }
        }
    }
}

// ========================= softmax (masked, scaled) =========================
__global__ __launch_bounds__(256)
void softmax_kernel()
{
    const size_t row = blockIdx.x;
    const int i = (int)(row & (QL - 1));
    float* s = g_score + row * KL;
    const int valid = ML + i + 1;
    const int t = threadIdx.x;
    __shared__ float red[256];

    float mx = -3.0e38f;
    for (int j = t; j < valid; j += 256) mx = fmaxf(mx, s[j]);
    red[t] = mx; __syncthreads();
#pragma unroll
    for (int o = 128; o > 0; o >>= 1) {
        if (t < o) red[t] = fmaxf(red[t], red[t + o]);
        __syncthreads();
    }
    mx = red[0];
    __syncthreads();

    float ev[8];
    float sum = 0.f;
    int cnt = 0;
    for (int j = t; j < valid; j += 256) {
        float e = __expf(0.125f * (s[j] - mx));
        ev[cnt++] = e;
        sum += e;
    }
    red[t] = sum; __syncthreads();
#pragma unroll
    for (int o = 128; o > 0; o >>= 1) {
        if (t < o) red[t] += red[t + o];
        __syncthreads();
    }
    const float inv = 1.f / red[0];

    cnt = 0;
    for (int j = t; j < valid; j += 256) s[j] = ev[cnt++] * inv;
    for (int j = t; j < KL; j += 256)
        if (j >= valid) s[j] = 0.f;
}

// ========================= P @ V (fp32, unchanged) ==========================
__global__ __launch_bounds__(256, 2)
void pv_kernel()
{
    const int bh = blockIdx.y;
    const int b  = bh >> 4;
    const int h  = bh & 15;
    const int i0 = blockIdx.x * 64;

    __shared__ float Ps[64][64];
    __shared__ float Vs[64][64];

    const int t    = threadIdx.x;
    const int lrow = t >> 2;
    const int lq   = (t & 3) * 4;
    const int tm   = (t >> 4) * 4;
    const int tn   = (t & 15) * 4;

    float acc[4][4];
#pragma unroll
    for (int i = 0; i < 4; ++i)
#pragma unroll
        for (int j = 0; j < 4; ++j) acc[i][j] = 0.f;

    const int jend = ML + i0 + 64;
    const float* prow  = g_score + ((size_t)bh * QL + i0 + lrow) * KL;
    const float* vbase = g_w + (size_t)(b * KL) * 3072 + DM + h * DH;

    for (int j0 = 0; j0 < jend; j0 += 64) {
#pragma unroll
        for (int it = 0; it < 4; ++it) {
            int jj = lq + it * 16;
            float4 p4 = *(const float4*)(prow + j0 + jj);
            Ps[jj + 0][lrow] = p4.x;
            Ps[jj + 1][lrow] = p4.y;
            Ps[jj + 2][lrow] = p4.z;
            Ps[jj + 3][lrow] = p4.w;
            int d = lq + it * 16;
            float4 v4 = *(const float4*)(vbase + (size_t)(j0 + lrow) * 3072 + d);
            *(float4*)&Vs[lrow][d] = v4;
        }
        __syncthreads();
#pragma unroll 16
        for (int jj = 0; jj < 64; ++jj) {
            float a[4], bb[4];
            *(float4*)a  = *(const float4*)&Ps[jj][tm];
            *(float4*)bb = *(const float4*)&Vs[jj][tn];
#pragma unroll
            for (int i = 0; i < 4; ++i)
#pragma unroll
                for (int j = 0; j < 4; ++j)
                    acc[i][j] = fmaf(a[i], bb[j], acc[i][j]);
        }
        __syncthreads();
    }

#pragma unroll
    for (int i = 0; i < 4; ++i) {
        size_t off = ((size_t)(b * QL) + i0 + tm + i) * DM + h * DH + tn;
        float4 o;
        o.x = acc[i][0]; o.y = acc[i][1]; o.z = acc[i][2]; o.w = acc[i][3];
        *(float4*)(g_attn + off) = o;
    }
}

// =========================== launch =======================================
extern "C" void kernel_launch(void* const* d_in, const int* in_sizes, int n_in,
                              void* d_out, int out_size)
{
    const float* inputs = (const float*)d_in[0];
    const float* mem    = (const float*)d_in[1];
    const float* r      = (const float*)d_in[2];
    const float* W_qkv  = (const float*)d_in[3];
    const float* b_qkv  = (const float*)d_in[4];
    const float* W_r    = (const float*)d_in[5];
    const float* b_r    = (const float*)d_in[6];
    const float* W_o    = (const float*)d_in[7];
    const float* b_o    = (const float*)d_in[8];
    const float* u      = (const float*)d_in[9];
    const float* v      = (const float*)d_in[10];
    float* out = (float*)d_out;

    float *pw, *prp, *pattn;
    __nv_bfloat16 *pah, *pal, *prh, *prl, *poh, *pol;
    __nv_bfloat16 *pwqh, *pwql, *pwrh, *pwrl, *pwoh, *pwol;
    cudaGetSymbolAddress((void**)&pw,    g_w);
    cudaGetSymbolAddress((void**)&prp,   g_rp);
    cudaGetSymbolAddress((void**)&pattn, g_attn);
    cudaGetSymbolAddress((void**)&pah,   g_ah);
    cudaGetSymbolAddress((void**)&pal,   g_al);
    cudaGetSymbolAddress((void**)&prh,   g_rh);
    cudaGetSymbolAddress((void**)&prl,   g_rl);
    cudaGetSymbolAddress((void**)&poh,   g_oh);
    cudaGetSymbolAddress((void**)&pol,   g_ol);
    cudaGetSymbolAddress((void**)&pwqh,  g_wqh);
    cudaGetSymbolAddress((void**)&pwql,  g_wql);
    cudaGetSymbolAddress((void**)&pwrh,  g_wrh);
    cudaGetSymbolAddress((void**)&pwrl,  g_wrl);
    cudaGetSymbolAddress((void**)&pwoh,  g_woh);
    cudaGetSymbolAddress((void**)&pwol,  g_wol);

    cudaFuncSetAttribute(gemm_bf3, cudaFuncAttributeMaxDynamicSharedMemorySize, GEMM_SMEM);

    dim3 blk(256);

    // --- prep: bf16 hi/lo splits ---
    split_concat<<<4096, blk>>>(mem, inputs, pah, pal);
    split_plain<<<4096, blk>>>(r, prh, prl);
    split_transpose<<<dim3(3072 / 32, 1024 / 32), blk>>>(W_qkv, pwqh, pwql, 3072);
    split_transpose<<<dim3(1024 / 32, 1024 / 32), blk>>>(W_r,   pwrh, pwrl, 1024);
    split_transpose<<<dim3(1024 / 32, 1024 / 32), blk>>>(W_o,   pwoh, pwol, 1024);

    // 1) w = cat(mem, inputs) @ W_qkv + b_qkv -> g_w [4096, 3072]
    gemm_bf3<<<dim3(3072 / 128, 4096 / 128), blk, GEMM_SMEM>>>(pah, pal, pwqh, pwql, b_qkv, pw, 3072);
    // 2) rp = r @ W_r + b_r -> g_rp [4096, 1024]
    gemm_bf3<<<dim3(1024 / 128, 4096 / 128), blk, GEMM_SMEM>>>(prh, prl, pwrh, pwrl, b_r, prp, 1024);
    // 3) AC content scores
    score_kernel<false><<<dim3(KL / 128, QL / 128, BQ * NH), blk>>>(u, v);
    // 4) BD position scores (rel-shifted scatter-add)
    score_kernel<true><<<dim3(KL / 128, QL / 128, BQ * NH), blk>>>(u, v);
    // 5) masked scaled softmax
    softmax_kernel<<<BQ * NH * QL, blk>>>();
    // 6) out_heads = P @ V -> g_attn [2048, 1024]
    pv_kernel<<<dim3(QL / 64, BQ * NH), blk>>>();
    // 7) final projection: g_attn @ W_o + b_o -> d_out
    split_plain<<<2048, blk>>>(pattn, poh, pol);
    gemm_bf3<<<dim3(1024 / 128, 2048 / 128), blk, GEMM_SMEM>>>(poh, pol, pwoh, pwol, b_o, out, 1024);
}

// round 4
// speedup vs baseline: 2.0915x; 1.5268x over previous
#include <cuda_runtime.h>
#include <cuda_bf16.h>
#include <cstdint>
#include <cstddef>

#define BQ 2
#define QL 1024
#define ML 1024
#define KL 2048
#define DM 1024
#define NH 16
#define DH 64

// ---------------- scratch (device globals: allocation-free) ----------------
__device__ float g_w[(size_t)4096 * 3072];          // cat @ W_qkv  [B*K, 3D]
__device__ float g_rp[(size_t)4096 * 1024];         // r @ W_r      [B*K, D]
__device__ float g_score[(size_t)32 * 1024 * 2048]; // AC [B*H, Q, K]
__device__ float g_bd[(size_t)32 * 1024 * 2048];    // BD-pre [B*H, Q, P]
__device__ float g_attn[(size_t)2048 * 1024];       // [B*Q, D]

// dense GEMM bf16 hi/lo splits
__device__ __nv_bfloat16 g_ah[(size_t)4096 * 1024], g_al[(size_t)4096 * 1024];
__device__ __nv_bfloat16 g_rh[(size_t)4096 * 1024], g_rl[(size_t)4096 * 1024];
__device__ __nv_bfloat16 g_oh[(size_t)2048 * 1024], g_ol[(size_t)2048 * 1024];
__device__ __nv_bfloat16 g_wqh[(size_t)3072 * 1024], g_wql[(size_t)3072 * 1024];
__device__ __nv_bfloat16 g_wrh[(size_t)1024 * 1024], g_wrl[(size_t)1024 * 1024];
__device__ __nv_bfloat16 g_woh[(size_t)1024 * 1024], g_wol[(size_t)1024 * 1024];

// per-head attention operands (bf16 hi/lo, K-major in d or j)
__device__ __nv_bfloat16 g_quh[(size_t)32 * 1024 * 64], g_qul[(size_t)32 * 1024 * 64];
__device__ __nv_bfloat16 g_qvh[(size_t)32 * 1024 * 64], g_qvl[(size_t)32 * 1024 * 64];
__device__ __nv_bfloat16 g_khh[(size_t)32 * 2048 * 64], g_khl[(size_t)32 * 2048 * 64];
__device__ __nv_bfloat16 g_rrh[(size_t)32 * 2048 * 64], g_rrl[(size_t)32 * 2048 * 64];
__device__ __nv_bfloat16 g_vth[(size_t)32 * 64 * 2048], g_vtl[(size_t)32 * 64 * 2048];
// softmax probabilities, bf16 hi/lo
__device__ __nv_bfloat16 g_ph[(size_t)32 * 1024 * 2048], g_pl[(size_t)32 * 1024 * 2048];

// ======================= helpers ===========================================
__device__ __forceinline__ uint32_t smem_u32(const void* p) {
    uint32_t a;
    asm("{ .reg .u64 t; cvta.to.shared.u64 t, %1; cvt.u32.u64 %0, t; }"
        : "=r"(a) : "l"(p));
    return a;
}
__device__ __forceinline__ void split1(float x, __nv_bfloat16& h, __nv_bfloat16& l) {
    h = __float2bfloat16_rn(x);
    l = __float2bfloat16_rn(x - __bfloat162float(h));
}
__device__ __forceinline__ void ldmx4(uint32_t a[4], uint32_t addr) {
    asm volatile("ldmatrix.sync.aligned.m8n8.x4.shared.b16 {%0,%1,%2,%3}, [%4];"
        : "=r"(a[0]), "=r"(a[1]), "=r"(a[2]), "=r"(a[3]) : "r"(addr));
}
__device__ __forceinline__ void ldmx2(uint32_t a[2], uint32_t addr) {
    asm volatile("ldmatrix.sync.aligned.m8n8.x2.shared.b16 {%0,%1}, [%2];"
        : "=r"(a[0]), "=r"(a[1]) : "r"(addr));
}
__device__ __forceinline__ void mma16816(float c[4], const uint32_t a[4], const uint32_t b[2]) {
    asm volatile("mma.sync.aligned.m16n8k16.row.col.f32.bf16.bf16.f32 "
        "{%0,%1,%2,%3}, {%4,%5,%6,%7}, {%8,%9}, {%0,%1,%2,%3};"
        : "+f"(c[0]), "+f"(c[1]), "+f"(c[2]), "+f"(c[3])
        : "r"(a[0]), "r"(a[1]), "r"(a[2]), "r"(a[3]), "r"(b[0]), "r"(b[1]));
}
#define CP16(dst, src) \
    asm volatile("cp.async.cg.shared.global [%0], [%1], 16;" :: "r"(dst), "l"(src) : "memory")
#define CP_COMMIT() asm volatile("cp.async.commit_group;" ::: "memory")
#define CP_WAIT(n)  asm volatile("cp.async.wait_group %0;" :: "n"(n) : "memory")

// ===================== prep: split kernels ==================================
__global__ __launch_bounds__(256)
void split_concat(const float* __restrict__ mem, const float* __restrict__ inp,
                  __nv_bfloat16* __restrict__ hi, __nv_bfloat16* __restrict__ lo)
{
    size_t idx = ((size_t)blockIdx.x * 256 + threadIdx.x) * 4;
    size_t row = idx >> 10;
    int col = (int)(idx & 1023);
    int b = (int)(row >> 11);
    int k = (int)(row & 2047);
    const float* src = (k < ML) ? mem + ((size_t)(b * ML + k) << 10)
                                : inp + ((size_t)(b * QL + (k - ML)) << 10);
    float4 v = *(const float4*)(src + col);
    __nv_bfloat16 h0, h1, h2, h3, l0, l1, l2, l3;
    split1(v.x, h0, l0); split1(v.y, h1, l1);
    split1(v.z, h2, l2); split1(v.w, h3, l3);
    __nv_bfloat162* H = (__nv_bfloat162*)(hi + idx);
    __nv_bfloat162* L = (__nv_bfloat162*)(lo + idx);
    H[0] = make_bfloat162(h0, h1); H[1] = make_bfloat162(h2, h3);
    L[0] = make_bfloat162(l0, l1); L[1] = make_bfloat162(l2, l3);
}

__global__ __launch_bounds__(256)
void split_plain(const float* __restrict__ src,
                 __nv_bfloat16* __restrict__ hi, __nv_bfloat16* __restrict__ lo)
{
    size_t idx = ((size_t)blockIdx.x * 256 + threadIdx.x) * 4;
    float4 v = *(const float4*)(src + idx);
    __nv_bfloat16 h0, h1, h2, h3, l0, l1, l2, l3;
    split1(v.x, h0, l0); split1(v.y, h1, l1);
    split1(v.z, h2, l2); split1(v.w, h3, l3);
    __nv_bfloat162* H = (__nv_bfloat162*)(hi + idx);
    __nv_bfloat162* L = (__nv_bfloat162*)(lo + idx);
    H[0] = make_bfloat162(h0, h1); H[1] = make_bfloat162(h2, h3);
    L[0] = make_bfloat162(l0, l1); L[1] = make_bfloat162(l2, l3);
}

__global__ __launch_bounds__(256)
void split_transpose(const float* __restrict__ in,
                     __nv_bfloat16* __restrict__ hi, __nv_bfloat16* __restrict__ lo, int N)
{
    __shared__ float s[32][33];
    const int nx = blockIdx.x * 32;
    const int ky = blockIdx.y * 32;
    const int tx = threadIdx.x & 31;
    const int ty = threadIdx.x >> 5;
#pragma unroll
    for (int r = 0; r < 32; r += 8)
        s[ty + r][tx] = in[(size_t)(ky + ty + r) * N + nx + tx];
    __syncthreads();
#pragma unroll
    for (int r = 0; r < 32; r += 8) {
        float x = s[tx][ty + r];
        __nv_bfloat16 h, l;
        split1(x, h, l);
        size_t o = (size_t)(nx + ty + r) * DM + ky + tx;
        hi[o] = h;
        lo[o] = l;
    }
}

// per-head operands: qu/qv (rows i), k/r (rows j), all [bh][row][64] K-major
__global__ __launch_bounds__(256)
void split_heads(const float* __restrict__ u, const float* __restrict__ v)
{
    size_t gid = (size_t)blockIdx.x * 256 + threadIdx.x;
    int d = (int)(gid & 15) * 4;
    int h = (int)(gid >> 4) & 15;
    int j = (int)(gid >> 8) & 2047;
    int b = (int)(gid >> 19);
    size_t wrow = (size_t)(b * KL + j);
    size_t orow = ((size_t)(b * NH + h) * KL + j) * DH + d;

    float4 kx = *(const float4*)(g_w + wrow * 3072 + 2 * DM + h * DH + d);
    float4 rx = *(const float4*)(g_rp + wrow * DM + h * DH + d);
    __nv_bfloat16 h0, l0, h1, l1, h2, l2, h3, l3;
    split1(kx.x, h0, l0); split1(kx.y, h1, l1); split1(kx.z, h2, l2); split1(kx.w, h3, l3);
    *(__nv_bfloat162*)(g_khh + orow)     = make_bfloat162(h0, h1);
    *(__nv_bfloat162*)(g_khh + orow + 2) = make_bfloat162(h2, h3);
    *(__nv_bfloat162*)(g_khl + orow)     = make_bfloat162(l0, l1);
    *(__nv_bfloat162*)(g_khl + orow + 2) = make_bfloat162(l2, l3);
    split1(rx.x, h0, l0); split1(rx.y, h1, l1); split1(rx.z, h2, l2); split1(rx.w, h3, l3);
    *(__nv_bfloat162*)(g_rrh + orow)     = make_bfloat162(h0, h1);
    *(__nv_bfloat162*)(g_rrh + orow + 2) = make_bfloat162(h2, h3);
    *(__nv_bfloat162*)(g_rrl + orow)     = make_bfloat162(l0, l1);
    *(__nv_bfloat162*)(g_rrl + orow + 2) = make_bfloat162(l2, l3);

    if (j >= ML) {
        int i = j - ML;
        size_t qrow = ((size_t)(b * NH + h) * QL + i) * DH + d;
        float4 qx = *(const float4*)(g_w + wrow * 3072 + h * DH + d);
        float4 ux = *(const float4*)(u + h * DH + d);
        float4 vx = *(const float4*)(v + h * DH + d);
        split1(qx.x + ux.x, h0, l0); split1(qx.y + ux.y, h1, l1);
        split1(qx.z + ux.z, h2, l2); split1(qx.w + ux.w, h3, l3);
        *(__nv_bfloat162*)(g_quh + qrow)     = make_bfloat162(h0, h1);
        *(__nv_bfloat162*)(g_quh + qrow + 2) = make_bfloat162(h2, h3);
        *(__nv_bfloat162*)(g_qul + qrow)     = make_bfloat162(l0, l1);
        *(__nv_bfloat162*)(g_qul + qrow + 2) = make_bfloat162(l2, l3);
        split1(qx.x + vx.x, h0, l0); split1(qx.y + vx.y, h1, l1);
        split1(qx.z + vx.z, h2, l2); split1(qx.w + vx.w, h3, l3);
        *(__nv_bfloat162*)(g_qvh + qrow)     = make_bfloat162(h0, h1);
        *(__nv_bfloat162*)(g_qvh + qrow + 2) = make_bfloat162(h2, h3);
        *(__nv_bfloat162*)(g_qvl + qrow)     = make_bfloat162(l0, l1);
        *(__nv_bfloat162*)(g_qvl + qrow + 2) = make_bfloat162(l2, l3);
    }
}

// V transposed per head: g_vt[bh][d][j]
__global__ __launch_bounds__(256)
void split_vt()
{
    __shared__ float s[64][65];
    const int bh = blockIdx.y;
    const int b = bh >> 4;
    const int h = bh & 15;
    const int j0 = blockIdx.x * 64;
    const int t = threadIdx.x;
#pragma unroll
    for (int it = 0; it < 4; ++it) {
        int jj = it * 16 + (t >> 4);
        int d = (t & 15) * 4;
        float4 x = *(const float4*)(g_w + (size_t)(b * KL + j0 + jj) * 3072 + DM + h * DH + d);
        s[jj][d] = x.x; s[jj][d + 1] = x.y; s[jj][d + 2] = x.z; s[jj][d + 3] = x.w;
    }
    __syncthreads();
#pragma unroll
    for (int it = 0; it < 4; ++it) {
        int d = it * 16 + (t >> 4);
        int jj = (t & 15) * 4;
        size_t o = ((size_t)bh * DH + d) * KL + j0 + jj;
        __nv_bfloat16 h0, l0, h1, l1, h2, l2, h3, l3;
        split1(s[jj][d], h0, l0); split1(s[jj + 1][d], h1, l1);
        split1(s[jj + 2][d], h2, l2); split1(s[jj + 3][d], h3, l3);
        *(__nv_bfloat162*)(g_vth + o)     = make_bfloat162(h0, h1);
        *(__nv_bfloat162*)(g_vth + o + 2) = make_bfloat162(h2, h3);
        *(__nv_bfloat162*)(g_vtl + o)     = make_bfloat162(l0, l1);
        *(__nv_bfloat162*)(g_vtl + o + 2) = make_bfloat162(l2, l3);
    }
}

// ============== dense GEMM: mma.sync bf16 3-term split ======================
#define RS 80
#define ARRB (128 * RS)
#define STGB (4 * ARRB)
#define NSTG 4
#define GEMM_SMEM (NSTG * STGB)

__global__ __launch_bounds__(256, 1)
void gemm_bf3(const __nv_bfloat16* __restrict__ Ah, const __nv_bfloat16* __restrict__ Al,
              const __nv_bfloat16* __restrict__ Bh, const __nv_bfloat16* __restrict__ Bl,
              const float* __restrict__ bias, float* __restrict__ C, int N)
{
    extern __shared__ char sm[];
    const uint32_t sb = smem_u32(sm);
    const int t = threadIdx.x;
    const int lane = t & 31;
    const int wid = t >> 5;
    const int m0 = blockIdx.y * 128;
    const int n0 = blockIdx.x * 128;
    const int warp_m = (wid & 1) * 64;
    const int warp_n = (wid >> 1) * 32;

    const __nv_bfloat16* srcs[4] = {
        Ah + (size_t)m0 * DM, Al + (size_t)m0 * DM,
        Bh + (size_t)n0 * DM, Bl + (size_t)n0 * DM
    };

    auto issue_stage = [&](int c) {
        uint32_t dst0 = sb + (uint32_t)(c & 3) * STGB;
#pragma unroll
        for (int arr = 0; arr < 4; ++arr) {
#pragma unroll
            for (int rep = 0; rep < 2; ++rep) {
                int ci = t + rep * 256;
                int row = ci >> 2;
                int kc = ci & 3;
                uint32_t dst = dst0 + arr * ARRB + row * RS + kc * 16;
                const __nv_bfloat16* src = srcs[arr] + (size_t)row * DM + c * 32 + kc * 8;
                CP16(dst, src);
            }
        }
    };

    float acc[4][4][4];
#pragma unroll
    for (int im = 0; im < 4; ++im)
#pragma unroll
        for (int jn = 0; jn < 4; ++jn)
#pragma unroll
            for (int q = 0; q < 4; ++q) acc[im][jn][q] = 0.f;

#pragma unroll
    for (int s = 0; s < NSTG - 1; ++s) { issue_stage(s); CP_COMMIT(); }

    const int NCH = DM / 32;
    for (int c = 0; c < NCH; ++c) {
        CP_WAIT(2);
        __syncthreads();
        if (c + 3 < NCH) issue_stage(c + 3);
        CP_COMMIT();

        const uint32_t st = sb + (uint32_t)(c & 3) * STGB;
        const int mrow = lane & 15;
        const int khalf = lane >> 4;
        const int nrow = lane & 7;
        const int khalfb = (lane >> 3) & 1;
#pragma unroll
        for (int kk = 0; kk < 32; kk += 16) {
            uint32_t ah[4][4], al[4][4], bh[4][2], bl[4][2];
#pragma unroll
            for (int im = 0; im < 4; ++im) {
                uint32_t aaddr = st + (warp_m + im * 16 + mrow) * RS + (kk + khalf * 8) * 2;
                ldmx4(ah[im], aaddr);
                ldmx4(al[im], aaddr + ARRB);
            }
#pragma unroll
            for (int jn = 0; jn < 4; ++jn) {
                uint32_t baddr = st + 2 * ARRB + (warp_n + jn * 8 + nrow) * RS + (kk + khalfb * 8) * 2;
                ldmx2(bh[jn], baddr);
                ldmx2(bl[jn], baddr + ARRB);
            }
#pragma unroll
            for (int im = 0; im < 4; ++im)
#pragma unroll
                for (int jn = 0; jn < 4; ++jn) {
                    mma16816(acc[im][jn], ah[im], bh[jn]);
                    mma16816(acc[im][jn], ah[im], bl[jn]);
                    mma16816(acc[im][jn], al[im], bh[jn]);
                }
        }
    }

#pragma unroll
    for (int im = 0; im < 4; ++im) {
        int m = m0 + warp_m + im * 16 + (lane >> 2);
#pragma unroll
        for (int jn = 0; jn < 4; ++jn) {
            int n = n0 + warp_n + jn * 8 + (lane & 3) * 2;
            float b0 = bias[n], b1 = bias[n + 1];
            float2 v0, v1;
            v0.x = acc[im][jn][0] + b0; v0.y = acc[im][jn][1] + b1;
            v1.x = acc[im][jn][2] + b0; v1.y = acc[im][jn][3] + b1;
            *(float2*)(C + (size_t)m * N + n) = v0;
            *(float2*)(C + (size_t)(m + 8) * N + n) = v1;
        }
    }
}

// ============== AC / BD score GEMM (mma, K=64 single shot) ==================
#define SRS 144                    // 64 bf16 = 128 B + 16 pad
#define SARRB (128 * SRS)          // 18432
#define SCORE_SMEM (4 * SARRB)     // 73728

template<bool IS_BD>
__global__ __launch_bounds__(256, 1)
void score_mma()
{
    const int bh = blockIdx.z;
    const int i0 = blockIdx.y * 128;
    const int p0 = blockIdx.x * 128;
    if (!IS_BD) {
        if (p0 > ML + i0 + 127) return;          // fully masked
    } else {
        if (i0 + p0 + 254 < QL - 1) return;      // all shifted targets j < 0
    }

    extern __shared__ char sm[];
    const uint32_t sb = smem_u32(sm);
    const int t = threadIdx.x;
    const int lane = t & 31;
    const int wid = t >> 5;
    const int warp_m = (wid & 1) * 64;
    const int warp_n = (wid >> 1) * 32;

    const __nv_bfloat16* srcs[4];
    if (!IS_BD) {
        srcs[0] = g_quh + ((size_t)bh * QL + i0) * DH;
        srcs[1] = g_qul + ((size_t)bh * QL + i0) * DH;
        srcs[2] = g_khh + ((size_t)bh * KL + p0) * DH;
        srcs[3] = g_khl + ((size_t)bh * KL + p0) * DH;
    } else {
        srcs[0] = g_qvh + ((size_t)bh * QL + i0) * DH;
        srcs[1] = g_qvl + ((size_t)bh * QL + i0) * DH;
        srcs[2] = g_rrh + ((size_t)bh * KL + p0) * DH;
        srcs[3] = g_rrl + ((size_t)bh * KL + p0) * DH;
    }
#pragma unroll
    for (int arr = 0; arr < 4; ++arr) {
#pragma unroll
        for (int rep = 0; rep < 4; ++rep) {
            int ci = t + rep * 256;              // 0..1023
            int row = ci >> 3;
            int kc = ci & 7;
            uint32_t dst = sb + arr * SARRB + row * SRS + kc * 16;
            CP16(dst, srcs[arr] + (size_t)row * DH + kc * 8);
        }
    }
    CP_COMMIT();
    CP_WAIT(0);
    __syncthreads();

    float acc[4][4][4];
#pragma unroll
    for (int im = 0; im < 4; ++im)
#pragma unroll
        for (int jn = 0; jn < 4; ++jn)
#pragma unroll
            for (int q = 0; q < 4; ++q) acc[im][jn][q] = 0.f;

    const int mrow = lane & 15;
    const int khalf = lane >> 4;
    const int nrow = lane & 7;
    const int khalfb = (lane >> 3) & 1;
#pragma unroll
    for (int kk = 0; kk < 64; kk += 16) {
        uint32_t ah[4][4], al[4][4], bh[4][2], bl[4][2];
#pragma unroll
        for (int im = 0; im < 4; ++im) {
            uint32_t aaddr = sb + (warp_m + im * 16 + mrow) * SRS + (kk + khalf * 8) * 2;
            ldmx4(ah[im], aaddr);
            ldmx4(al[im], aaddr + SARRB);
        }
#pragma unroll
        for (int jn = 0; jn < 4; ++jn) {
            uint32_t baddr = sb + 2 * SARRB + (warp_n + jn * 8 + nrow) * SRS + (kk + khalfb * 8) * 2;
            ldmx2(bh[jn], baddr);
            ldmx2(bl[jn], baddr + SARRB);
        }
#pragma unroll
        for (int im = 0; im < 4; ++im)
#pragma unroll
            for (int jn = 0; jn < 4; ++jn) {
                mma16816(acc[im][jn], ah[im], bh[jn]);
                mma16816(acc[im][jn], ah[im], bl[jn]);
                mma16816(acc[im][jn], al[im], bh[jn]);
            }
    }

    float* OUT = IS_BD ? g_bd : g_score;
#pragma unroll
    for (int im = 0; im < 4; ++im) {
        int m = i0 + warp_m + im * 16 + (lane >> 2);
        float* r0 = OUT + ((size_t)bh * QL + m) * KL + p0;
        float* r1 = OUT + ((size_t)bh * QL + m + 8) * KL + p0;
#pragma unroll
        for (int jn = 0; jn < 4; ++jn) {
            int n = warp_n + jn * 8 + (lane & 3) * 2;
            *(float2*)(r0 + n) = make_float2(acc[im][jn][0], acc[im][jn][1]);
            *(float2*)(r1 + n) = make_float2(acc[im][jn][2], acc[im][jn][3]);
        }
    }
}

// ===== softmax: gather BD at shifted offset, masked, emit bf16 hi/lo P ======
__global__ __launch_bounds__(256)
void softmax_kernel()
{
    const size_t row = blockIdx.x;
    const int i = (int)(row & (QL - 1));
    const float* ac = g_score + row * KL;
    const float* bd = g_bd + row * KL + (QL - 1 - i);   // bd[j] at p = j + Q-1-i
    __nv_bfloat16* ph = g_ph + row * KL;
    __nv_bfloat16* pl = g_pl + row * KL;
    const int valid = ML + i + 1;
    const int zend = ML + (i | 127) + 1;                 // PV reads up to here
    const int t = threadIdx.x;
    __shared__ float red[256];

    float sv[8];
    float mx = -3.0e38f;
    int cnt = 0;
    for (int j = t; j < valid; j += 256) {
        float s = 0.125f * (ac[j] + bd[j]);
        sv[cnt++] = s;
        mx = fmaxf(mx, s);
    }
    red[t] = mx; __syncthreads();
#pragma unroll
    for (int o = 128; o > 0; o >>= 1) {
        if (t < o) red[t] = fmaxf(red[t], red[t + o]);
        __syncthreads();
    }
    mx = red[0];
    __syncthreads();

    float sum = 0.f;
#pragma unroll
    for (int q = 0; q < cnt; ++q) {
        sv[q] = __expf(sv[q] - mx);
        sum += sv[q];
    }
    red[t] = sum; __syncthreads();
#pragma unroll
    for (int o = 128; o > 0; o >>= 1) {
        if (t < o) red[t] += red[t + o];
        __syncthreads();
    }
    const float inv = 1.f / red[0];

    cnt = 0;
    for (int j = t; j < valid; j += 256) {
        float p = sv[cnt++] * inv;
        __nv_bfloat16 h, l;
        split1(p, h, l);
        ph[j] = h;
        pl[j] = l;
    }
    for (int j = t; j < zend; j += 256) {
        if (j >= valid) {
            ph[j] = __float2bfloat16_rn(0.f);
            pl[j] = __float2bfloat16_rn(0.f);
        }
    }
}

// =================== P @ V (mma, 128 x 64, j-chunks of 32) ==================
#define PV_PB (128 * 80)                       // P array bytes per stage
#define PV_VB (64 * 80)                        // V array bytes per stage
#define PV_STG (2 * PV_PB + 2 * PV_VB)         // 30720
#define PV_NSTG 4
#define PV_SMEM (PV_NSTG * PV_STG)             // 122880

__global__ __launch_bounds__(256, 1)
void pv_mma()
{
    extern __shared__ char sm[];
    const uint32_t sb = smem_u32(sm);
    const int bh = blockIdx.y;
    const int b = bh >> 4;
    const int h = bh & 15;
    const int i0 = blockIdx.x * 128;
    const int t = threadIdx.x;
    const int lane = t & 31;
    const int wid = t >> 5;
    const int warp_m = (wid & 1) * 64;
    const int warp_n = (wid >> 1) * 16;

    const __nv_bfloat16* Ph = g_ph + ((size_t)bh * QL + i0) * KL;
    const __nv_bfloat16* Pl = g_pl + ((size_t)bh * QL + i0) * KL;
    const __nv_bfloat16* Vh = g_vth + (size_t)bh * DH * KL;
    const __nv_bfloat16* Vl = g_vtl + (size_t)bh * DH * KL;

    const int nch = (ML + i0 + 128) / 32;

    auto issue_stage = [&](int c) {
        uint32_t dst0 = sb + (uint32_t)(c & 3) * PV_STG;
        {
            int row = t >> 1, kc = t & 1;        // 128 rows x 2 chunks... need 4 chunks/row
        }
        // P arrays: 128 rows x 4 chunks (32 bf16 = 64 B) => 512 per array
#pragma unroll
        for (int rep = 0; rep < 2; ++rep) {
            int ci = t + rep * 256;
            int row = ci >> 2;
            int kc = ci & 3;
            uint32_t o = row * 80 + kc * 16;
            CP16(dst0 + o, Ph + (size_t)row * KL + c * 32 + kc * 8);
            CP16(dst0 + PV_PB + o, Pl + (size_t)row * KL + c * 32 + kc * 8);
        }
        // V arrays: 64 rows x 4 chunks => 256 per array
        {
            int row = t >> 2;
            int kc = t & 3;
            uint32_t o = row * 80 + kc * 16;
            CP16(dst0 + 2 * PV_PB + o, Vh + (size_t)row * KL + c * 32 + kc * 8);
            CP16(dst0 + 2 * PV_PB + PV_VB + o, Vl + (size_t)row * KL + c * 32 + kc * 8);
        }
    };

    float acc[4][2][4];
#pragma unroll
    for (int im = 0; im < 4; ++im)
#pragma unroll
        for (int jn = 0; jn < 2; ++jn)
#pragma unroll
            for (int q = 0; q < 4; ++q) acc[im][jn][q] = 0.f;

#pragma unroll
    for (int s = 0; s < PV_NSTG - 1; ++s) {
        if (s < nch) issue_stage(s);
        CP_COMMIT();
    }

    const int mrow = lane & 15;
    const int khalf = lane >> 4;
    const int nrow = lane & 7;
    const int khalfb = (lane >> 3) & 1;

    for (int c = 0; c < nch; ++c) {
        CP_WAIT(2);
        __syncthreads();
        if (c + 3 < nch) issue_stage(c + 3);
        CP_COMMIT();

        const uint32_t st = sb + (uint32_t)(c & 3) * PV_STG;
#pragma unroll
        for (int kk = 0; kk < 32; kk += 16) {
            uint32_t ah[4][4], al[4][4], bh[2][2], bl[2][2];
#pragma unroll
            for (int im = 0; im < 4; ++im) {
                uint32_t aaddr = st + (warp_m + im * 16 + mrow) * 80 + (kk + khalf * 8) * 2;
                ldmx4(ah[im], aaddr);
                ldmx4(al[im], aaddr + PV_PB);
            }
#pragma unroll
            for (int jn = 0; jn < 2; ++jn) {
                uint32_t baddr = st + 2 * PV_PB + (warp_n + jn * 8 + nrow) * 80 + (kk + khalfb * 8) * 2;
                ldmx2(bh[jn], baddr);
                ldmx2(bl[jn], baddr + PV_VB);
            }
#pragma unroll
            for (int im = 0; im < 4; ++im)
#pragma unroll
                for (int jn = 0; jn < 2; ++jn) {
                    mma16816(acc[im][jn], ah[im], bh[jn]);
                    mma16816(acc[im][jn], ah[im], bl[jn]);
                    mma16816(acc[im][jn], al[im], bh[jn]);
                }
        }
        __syncthreads();
    }

#pragma unroll
    for (int im = 0; im < 4; ++im) {
        int m = i0 + warp_m + im * 16 + (lane >> 2);
        float* r0 = g_attn + (size_t)(b * QL + m) * DM + h * DH;
        float* r1 = g_attn + (size_t)(b * QL + m + 8) * DM + h * DH;
#pragma unroll
        for (int jn = 0; jn < 2; ++jn) {
            int n = warp_n + jn * 8 + (lane & 3) * 2;
            *(float2*)(r0 + n) = make_float2(acc[im][jn][0], acc[im][jn][1]);
            *(float2*)(r1 + n) = make_float2(acc[im][jn][2], acc[im][jn][3]);
        }
    }
}

// =========================== launch =======================================
extern "C" void kernel_launch(void* const* d_in, const int* in_sizes, int n_in,
                              void* d_out, int out_size)
{
    const float* inputs = (const float*)d_in[0];
    const float* mem    = (const float*)d_in[1];
    const float* r      = (const float*)d_in[2];
    const float* W_qkv  = (const float*)d_in[3];
    const float* b_qkv  = (const float*)d_in[4];
    const float* W_r    = (const float*)d_in[5];
    const float* b_r    = (const float*)d_in[6];
    const float* W_o    = (const float*)d_in[7];
    const float* b_o    = (const float*)d_in[8];
    const float* u      = (const float*)d_in[9];
    const float* v      = (const float*)d_in[10];
    float* out = (float*)d_out;

    float *pw, *prp, *pattn;
    __nv_bfloat16 *pah, *pal, *prh, *prl, *poh, *pol;
    __nv_bfloat16 *pwqh, *pwql, *pwrh, *pwrl, *pwoh, *pwol;
    cudaGetSymbolAddress((void**)&pw,    g_w);
    cudaGetSymbolAddress((void**)&prp,   g_rp);
    cudaGetSymbolAddress((void**)&pattn, g_attn);
    cudaGetSymbolAddress((void**)&pah,   g_ah);
    cudaGetSymbolAddress((void**)&pal,   g_al);
    cudaGetSymbolAddress((void**)&prh,   g_rh);
    cudaGetSymbolAddress((void**)&prl,   g_rl);
    cudaGetSymbolAddress((void**)&poh,   g_oh);
    cudaGetSymbolAddress((void**)&pol,   g_ol);
    cudaGetSymbolAddress((void**)&pwqh,  g_wqh);
    cudaGetSymbolAddress((void**)&pwql,  g_wql);
    cudaGetSymbolAddress((void**)&pwrh,  g_wrh);
    cudaGetSymbolAddress((void**)&pwrl,  g_wrl);
    cudaGetSymbolAddress((void**)&pwoh,  g_woh);
    cudaGetSymbolAddress((void**)&pwol,  g_wol);

    cudaFuncSetAttribute(gemm_bf3, cudaFuncAttributeMaxDynamicSharedMemorySize, GEMM_SMEM);
    cudaFuncSetAttribute(score_mma<false>, cudaFuncAttributeMaxDynamicSharedMemorySize, SCORE_SMEM);
    cudaFuncSetAttribute(score_mma<true>,  cudaFuncAttributeMaxDynamicSharedMemorySize, SCORE_SMEM);
    cudaFuncSetAttribute(pv_mma, cudaFuncAttributeMaxDynamicSharedMemorySize, PV_SMEM);

    dim3 blk(256);

    // --- dense GEMM input splits ---
    split_concat<<<4096, blk>>>(mem, inputs, pah, pal);
    split_plain<<<4096, blk>>>(r, prh, prl);
    split_transpose<<<dim3(3072 / 32, 1024 / 32), blk>>>(W_qkv, pwqh, pwql, 3072);
    split_transpose<<<dim3(1024 / 32, 1024 / 32), blk>>>(W_r,   pwrh, pwrl, 1024);
    split_transpose<<<dim3(1024 / 32, 1024 / 32), blk>>>(W_o,   pwoh, pwol, 1024);

    // 1) w = cat @ W_qkv + b_qkv ; 2) rp = r @ W_r + b_r
    gemm_bf3<<<dim3(3072 / 128, 4096 / 128), blk, GEMM_SMEM>>>(pah, pal, pwqh, pwql, b_qkv, pw, 3072);
    gemm_bf3<<<dim3(1024 / 128, 4096 / 128), blk, GEMM_SMEM>>>(prh, prl, pwrh, pwrl, b_r, prp, 1024);

    // --- per-head attention operand splits ---
    split_heads<<<4096, blk>>>(u, v);
    split_vt<<<dim3(KL / 64, BQ * NH), blk>>>();

    // 3) AC -> g_score ; 4) BD -> g_bd
    score_mma<false><<<dim3(KL / 128, QL / 128, BQ * NH), blk, SCORE_SMEM>>>();
    score_mma<true><<<dim3(KL / 128, QL / 128, BQ * NH), blk, SCORE_SMEM>>>();

    // 5) softmax (AC + shifted-gather BD) -> P bf16 hi/lo
    softmax_kernel<<<BQ * NH * QL, blk>>>();

    // 6) out_heads = P @ V -> g_attn
    pv_mma<<<dim3(QL / 128, BQ * NH), blk, PV_SMEM>>>();

    // 7) final projection
    split_plain<<<2048, blk>>>(pattn, poh, pol);
    gemm_bf3<<<dim3(1024 / 128, 2048 / 128), blk, GEMM_SMEM>>>(poh, pol, pwoh, pwol, b_o, out, 1024);
}